// round 4
// baseline (speedup 1.0000x reference)
#include <cuda_runtime.h>
#include <cstdint>

typedef unsigned long long ull;

// Problem constants
constexpr int NB = 16, NN = 8192, NPOINT = 1024, NSAMPLE = 32;
constexpr int M_TOTAL = NB * NPOINT * NSAMPLE;       // 524288 positions
constexpr float INV_N = 1.0f / (float)M_TOTAL;       // 2^-19, exact
constexpr int NEWXYZ_ELEMS = NB * NPOINT * 3;        // 49152

// -------- scratch (device globals; no allocation allowed) --------
__device__ float g_y1[(size_t)M_TOTAL * 64];
__device__ float g_y2[(size_t)M_TOTAL * 64];
__device__ float g_y3[(size_t)M_TOTAL * 128];
__device__ int   g_idx[M_TOTAL];
__device__ float g_part1[4096 * 128];
__device__ float g_part2[4096 * 128];
__device__ float g_part3[8192 * 128];
__device__ float g_sum1[64],  g_ssq1[64];
__device__ float g_sum2[64],  g_ssq2[64];
__device__ float g_sum3[128], g_ssq3[128];

// ---------------- helpers ----------------
__device__ __forceinline__ void ffma2(ull& d, ull a, ull b) {
    asm("fma.rn.f32x2 %0, %1, %2, %0;" : "+l"(d) : "l"(a), "l"(b));
}
__device__ __forceinline__ float hadd2(ull v) {
    float lo, hi;
    asm("mov.b64 {%0, %1}, %2;" : "=f"(lo), "=f"(hi) : "l"(v));
    return lo + hi;
}
// TF32 rounding (round-to-nearest-away), matching the tensor-core input path.
__device__ __forceinline__ float to_tf32(float x) {
    unsigned u;
    asm("cvt.rna.tf32.f32 %0, %1;" : "=r"(u) : "f"(x));
    return __uint_as_float(u);
}
// XLA-GPU contracted squared distance: fma chain in axis order.
__device__ __forceinline__ float sqdist3(float dx, float dy, float dz) {
    return fmaf(dz, dz, fmaf(dy, dy, __fmul_rn(dx, dx)));
}

// ---------------- 1) farthest point sampling ----------------
__global__ void __launch_bounds__(1024) fps_kernel(const float* __restrict__ xyz,
                                                   float* __restrict__ newxyz) {
    const int b = blockIdx.x, tid = threadIdx.x;
    const float* X = xyz + (size_t)b * NN * 3;
    float px[8], py[8], pz[8], dd[8];
#pragma unroll
    for (int j = 0; j < 8; j++) {
        int p = tid * 8 + j;
        px[j] = X[p * 3 + 0]; py[j] = X[p * 3 + 1]; pz[j] = X[p * 3 + 2];
        dd[j] = 1e10f;
    }
    __shared__ float sc[3];
    __shared__ int sF;
    __shared__ float swv[32];
    __shared__ int swi[32];
    if (tid == 0) { sc[0] = px[0]; sc[1] = py[0]; sc[2] = pz[0]; }
    __syncthreads();

    float* outb = newxyz + (size_t)b * NPOINT * 3;
    const int lane = tid & 31, wid = tid >> 5;

    for (int it = 0; it < NPOINT; ++it) {
        if (tid == 0) {
            outb[it * 3 + 0] = sc[0];
            outb[it * 3 + 1] = sc[1];
            outb[it * 3 + 2] = sc[2];
        }
        const float cx = sc[0], cy = sc[1], cz = sc[2];
        float best = -1.0f; int bi = 0;
#pragma unroll
        for (int j = 0; j < 8; j++) {
            float dx = __fsub_rn(px[j], cx);
            float dy = __fsub_rn(py[j], cy);
            float dz = __fsub_rn(pz[j], cz);
            float d = sqdist3(dx, dy, dz);
            float nd = fminf(dd[j], d);
            dd[j] = nd;
            if (nd > best) { best = nd; bi = tid * 8 + j; }
        }
#pragma unroll
        for (int off = 16; off; off >>= 1) {
            float ov = __shfl_down_sync(0xffffffffu, best, off);
            int   oi = __shfl_down_sync(0xffffffffu, bi, off);
            if (ov > best || (ov == best && oi < bi)) { best = ov; bi = oi; }
        }
        if (lane == 0) { swv[wid] = best; swi[wid] = bi; }
        __syncthreads();
        if (wid == 0) {
            float v = swv[lane]; int ii = swi[lane];
#pragma unroll
            for (int off = 16; off; off >>= 1) {
                float ov = __shfl_down_sync(0xffffffffu, v, off);
                int   oi = __shfl_down_sync(0xffffffffu, ii, off);
                if (ov > v || (ov == v && oi < ii)) { v = ov; ii = oi; }
            }
            if (lane == 0) sF = ii;
        }
        __syncthreads();
        int f = sF;
        if ((f >> 3) == tid) {
            int j = f & 7;
            sc[0] = px[j]; sc[1] = py[j]; sc[2] = pz[j];
        }
        __syncthreads();
    }
}

// ---------------- 2) ball query ----------------
__global__ void __launch_bounds__(256) ball_kernel(const float* __restrict__ xyz,
                                                   const float* __restrict__ newxyz,
                                                   int* __restrict__ gidx) {
    const int gwarp = (blockIdx.x * blockDim.x + threadIdx.x) >> 5;
    const int lane = threadIdx.x & 31;
    if (gwarp >= NB * NPOINT) return;
    const int b = gwarp >> 10;
    const float R2 = (float)(0.2 * 0.2);

    const float cx = newxyz[gwarp * 3 + 0];
    const float cy = newxyz[gwarp * 3 + 1];
    const float cz = newxyz[gwarp * 3 + 2];
    const float* X = xyz + (size_t)b * NN * 3;
    int* out = gidx + (size_t)gwarp * NSAMPLE;

    int cnt = 0;
    int first = NN - 1;  // fallback (cnt==0 cannot happen: self is in-radius)
    for (int base = 0; base < NN; base += 32) {
        int j = base + lane;
        float dx = __fsub_rn(cx, X[j * 3 + 0]);
        float dy = __fsub_rn(cy, X[j * 3 + 1]);
        float dz = __fsub_rn(cz, X[j * 3 + 2]);
        float sq = sqdist3(dx, dy, dz);
        bool in = !(sq > R2);
        unsigned mask = __ballot_sync(0xffffffffu, in);
        if (mask) {
            if (cnt == 0) first = base + __ffs(mask) - 1;
            if (in) {
                int slot = cnt + __popc(mask & ((1u << lane) - 1u));
                if (slot < NSAMPLE) out[slot] = j;
            }
            cnt += __popc(mask);
            if (cnt >= NSAMPLE) break;
        }
    }
    if (cnt < NSAMPLE && lane >= cnt) out[lane] = first;
}

// ---------------- 3) fused GEMM (+BN-apply on load, +stats partials) ----------------
// MODE 1: gather grouped features (67 ch) -> y1.  MODE 2: y1->y2.  MODE 3: y2->y3.
// Inputs rounded to TF32 (matches JAX GPU default matmul precision); fp32 FMA accum.
template <int CPAD, int MODE>
__global__ void __launch_bounds__(256, 2) gemm_kernel(
    const float* __restrict__ xyz, const float* __restrict__ points,
    const float* __restrict__ newxyz, const int* __restrict__ gidx,
    const float* __restrict__ yin,
    const float* __restrict__ psum, const float* __restrict__ pssq,
    const float* __restrict__ pg, const float* __restrict__ pbe,
    const float* __restrict__ W, const float* __restrict__ bias,
    float* __restrict__ yout, float* __restrict__ part) {
    constexpr int CIN = (MODE == 1) ? 67 : 64;
    constexpr int OSTRIDE = (MODE == 3) ? 128 : 64;
    extern __shared__ float smem[];
    float* Ws = smem;                  // [64][CPAD]
    float* Xs = smem + 64 * CPAD;      // [128][CPAD]
    __shared__ int sIdx[128];
    __shared__ float sNew[4][3];
    __shared__ float sSc[64], sSh[64];

    const int tid = threadIdx.x;
    int m_tile, obase;
    if (MODE == 3) { m_tile = blockIdx.x >> 1; obase = (blockIdx.x & 1) << 6; }
    else           { m_tile = blockIdx.x;      obase = 0; }
    const int m0 = m_tile * 128;

    for (int e = tid; e < 64 * CPAD; e += 256) {
        int o = e / CPAD, c = e - o * CPAD;
        Ws[e] = (c < CIN) ? to_tf32(W[(obase + o) * CIN + c]) : 0.0f;
    }

    if (MODE == 1) {
        if (tid < 128) sIdx[tid] = gidx[m0 + tid];
        if (tid < 12) ((float*)sNew)[tid] = newxyz[(m0 >> 5) * 3 + tid];
    } else {
        if (tid < 64) {
            float s = psum[tid], ss = pssq[tid];
            float mean = s * INV_N;
            float var = ss * INV_N - mean * mean;
            float inv = rsqrtf(var + 1e-5f);
            float scv = pg[tid] * inv;
            sSc[tid] = scv;
            sSh[tid] = pbe[tid] - mean * scv;
        }
    }
    __syncthreads();

    if (MODE == 1) {
        const int bb = m0 >> 15;
        const float* Xb = xyz + (size_t)bb * NN * 3;
        const float* Pb = points + (size_t)bb * NN * 64;
        for (int e = tid; e < 128 * CPAD; e += 256) {
            int m = e / CPAD, c = e - m * CPAD;
            int gi = sIdx[m];
            float v;
            if (c < 3)       v = __fsub_rn(Xb[gi * 3 + c], sNew[m >> 5][c]);
            else if (c < 67) v = Pb[(size_t)gi * 64 + (c - 3)];
            else             v = 0.0f;
            Xs[m * CPAD + c] = to_tf32(v);
        }
    } else {
        for (int e = tid; e < 128 * 16; e += 256) {
            int m = e >> 4, cq = e & 15, c = cq * 4;
            float4 v = *reinterpret_cast<const float4*>(&yin[((size_t)(m0 + m)) * 64 + c]);
            v.x = to_tf32(fmaxf(fmaf(v.x, sSc[c + 0], sSh[c + 0]), 0.0f));
            v.y = to_tf32(fmaxf(fmaf(v.y, sSc[c + 1], sSh[c + 1]), 0.0f));
            v.z = to_tf32(fmaxf(fmaf(v.z, sSc[c + 2], sSh[c + 2]), 0.0f));
            v.w = to_tf32(fmaxf(fmaf(v.w, sSc[c + 3], sSh[c + 3]), 0.0f));
            *reinterpret_cast<float4*>(&Xs[m * 64 + c]) = v;
        }
    }
    __syncthreads();

    const int mg = tid & 15, og = tid >> 4;
    ull acc[32];
#pragma unroll
    for (int i = 0; i < 32; i++) acc[i] = 0ULL;

    for (int c = 0; c < CPAD; c += 4) {
        ull wv[8];
#pragma unroll
        for (int j = 0; j < 4; j++) {
            const ull* wp = reinterpret_cast<const ull*>(&Ws[(og * 4 + j) * CPAD + c]);
            wv[2 * j] = wp[0]; wv[2 * j + 1] = wp[1];
        }
#pragma unroll
        for (int i = 0; i < 8; i++) {
            const ull* xp = reinterpret_cast<const ull*>(&Xs[(mg + 16 * i) * CPAD + c]);
            ull x0 = xp[0], x1 = xp[1];
#pragma unroll
            for (int j = 0; j < 4; j++) {
                ffma2(acc[i * 4 + j], x0, wv[2 * j]);
                ffma2(acc[i * 4 + j], x1, wv[2 * j + 1]);
            }
        }
    }

    float bj[4];
#pragma unroll
    for (int j = 0; j < 4; j++) bj[j] = bias[obase + og * 4 + j];
    float sums[4] = {0, 0, 0, 0}, ssqs[4] = {0, 0, 0, 0};
#pragma unroll
    for (int i = 0; i < 8; i++) {
        float y[4];
#pragma unroll
        for (int j = 0; j < 4; j++) {
            float v = hadd2(acc[i * 4 + j]) + bj[j];
            y[j] = v;
            sums[j] += v;
            ssqs[j] += v * v;
        }
        *reinterpret_cast<float4*>(
            &yout[((size_t)(m0 + mg + 16 * i)) * OSTRIDE + obase + og * 4]) =
            make_float4(y[0], y[1], y[2], y[3]);
    }
#pragma unroll
    for (int off = 8; off; off >>= 1) {
#pragma unroll
        for (int j = 0; j < 4; j++) {
            sums[j] += __shfl_down_sync(0xffffffffu, sums[j], off);
            ssqs[j] += __shfl_down_sync(0xffffffffu, ssqs[j], off);
        }
    }
    if (mg == 0) {
#pragma unroll
        for (int j = 0; j < 4; j++) {
            part[blockIdx.x * 128 + og * 4 + j] = sums[j];
            part[blockIdx.x * 128 + 64 + og * 4 + j] = ssqs[j];
        }
    }
}

// ---------------- 4) deterministic stats reduction ----------------
__global__ void __launch_bounds__(256) reduce_stats(const float* __restrict__ part,
                                                    float* __restrict__ osum,
                                                    float* __restrict__ ossq,
                                                    int count, int rowstep) {
    const int ch = blockIdx.x;
    const int row0 = (rowstep == 2) ? (ch >> 6) : 0;
    const int lc = ch & 63;
    float s = 0.0f, ss = 0.0f;
    for (int i = threadIdx.x; i < count; i += 256) {
        int row = row0 + i * rowstep;
        s += part[row * 128 + lc];
        ss += part[row * 128 + 64 + lc];
    }
    __shared__ float as[8], bs[8];
#pragma unroll
    for (int off = 16; off; off >>= 1) {
        s += __shfl_down_sync(0xffffffffu, s, off);
        ss += __shfl_down_sync(0xffffffffu, ss, off);
    }
    const int lane = threadIdx.x & 31, wid = threadIdx.x >> 5;
    if (lane == 0) { as[wid] = s; bs[wid] = ss; }
    __syncthreads();
    if (threadIdx.x == 0) {
        float S = 0.0f, SS = 0.0f;
        for (int w = 0; w < 8; w++) { S += as[w]; SS += bs[w]; }
        osum[ch] = S; ossq[ch] = SS;
    }
}

// ---------------- 5) BN3 + ReLU + max over k ----------------
__global__ void __launch_bounds__(128) final_kernel(const float* __restrict__ y3,
                                                    const float* __restrict__ psum,
                                                    const float* __restrict__ pssq,
                                                    const float* __restrict__ pg,
                                                    const float* __restrict__ pbe,
                                                    float* __restrict__ out) {
    const int q = blockIdx.x;      // b*1024 + s
    const int o = threadIdx.x;     // channel 0..127
    float s = psum[o], ss = pssq[o];
    float mean = s * INV_N;
    float var = ss * INV_N - mean * mean;
    float inv = rsqrtf(var + 1e-5f);
    float scv = pg[o] * inv;
    float sh = pbe[o] - mean * scv;
    const float* base = y3 + (size_t)q * NSAMPLE * 128;
    float mx = -1e30f;
#pragma unroll 8
    for (int k = 0; k < NSAMPLE; k++) {
        float v = base[k * 128 + o];
        v = fmaxf(fmaf(v, scv, sh), 0.0f);
        mx = fmaxf(mx, v);
    }
    const int b = q >> 10, si = q & 1023;
    out[NEWXYZ_ELEMS + ((size_t)(b * 128 + o)) * 1024 + si] = mx;
}

// ---------------- launch ----------------
extern "C" void kernel_launch(void* const* d_in, const int* in_sizes, int n_in,
                              void* d_out, int out_size) {
    const float* xyz    = (const float*)d_in[0];
    const float* points = (const float*)d_in[1];
    const float* w1 = (const float*)d_in[2];
    const float* b1 = (const float*)d_in[3];
    const float* g1 = (const float*)d_in[4];
    const float* be1 = (const float*)d_in[5];
    const float* w2 = (const float*)d_in[6];
    const float* b2 = (const float*)d_in[7];
    const float* g2 = (const float*)d_in[8];
    const float* be2 = (const float*)d_in[9];
    const float* w3 = (const float*)d_in[10];
    const float* b3 = (const float*)d_in[11];
    const float* g3 = (const float*)d_in[12];
    const float* be3 = (const float*)d_in[13];
    float* out = (float*)d_out;

    float *y1, *y2, *y3, *p1, *p2, *p3;
    float *s1, *q1, *s2, *q2, *s3, *q3;
    int* idx;
    cudaGetSymbolAddress((void**)&y1, g_y1);
    cudaGetSymbolAddress((void**)&y2, g_y2);
    cudaGetSymbolAddress((void**)&y3, g_y3);
    cudaGetSymbolAddress((void**)&idx, g_idx);
    cudaGetSymbolAddress((void**)&p1, g_part1);
    cudaGetSymbolAddress((void**)&p2, g_part2);
    cudaGetSymbolAddress((void**)&p3, g_part3);
    cudaGetSymbolAddress((void**)&s1, g_sum1);
    cudaGetSymbolAddress((void**)&q1, g_ssq1);
    cudaGetSymbolAddress((void**)&s2, g_sum2);
    cudaGetSymbolAddress((void**)&q2, g_ssq2);
    cudaGetSymbolAddress((void**)&s3, g_sum3);
    cudaGetSymbolAddress((void**)&q3, g_ssq3);

    const int smem1 = (64 + 128) * 68 * 4;  // 52224
    const int smem2 = (64 + 128) * 64 * 4;  // 49152
    cudaFuncSetAttribute(gemm_kernel<68, 1>, cudaFuncAttributeMaxDynamicSharedMemorySize, smem1);
    cudaFuncSetAttribute(gemm_kernel<64, 2>, cudaFuncAttributeMaxDynamicSharedMemorySize, smem2);
    cudaFuncSetAttribute(gemm_kernel<64, 3>, cudaFuncAttributeMaxDynamicSharedMemorySize, smem2);

    // 1) FPS -> new_xyz (first 49152 elems of out)
    fps_kernel<<<NB, 1024>>>(xyz, out);
    // 2) ball query -> g_idx
    ball_kernel<<<(NB * NPOINT * 32) / 256, 256>>>(xyz, out, idx);
    // 3) layer1 (gather 67ch -> 64) + partial stats
    gemm_kernel<68, 1><<<M_TOTAL / 128, 256, smem1>>>(
        xyz, points, out, idx, nullptr, nullptr, nullptr, nullptr, nullptr,
        w1, b1, y1, p1);
    reduce_stats<<<64, 256>>>(p1, s1, q1, 4096, 1);
    // 4) layer2 (BN1+relu fused on load)
    gemm_kernel<64, 2><<<M_TOTAL / 128, 256, smem2>>>(
        nullptr, nullptr, nullptr, nullptr, y1, s1, q1, g1, be1,
        w2, b2, y2, p2);
    reduce_stats<<<64, 256>>>(p2, s2, q2, 4096, 1);
    // 5) layer3 (BN2+relu fused on load, O=128 split over 2 blocks/tile)
    gemm_kernel<64, 3><<<2 * (M_TOTAL / 128), 256, smem2>>>(
        nullptr, nullptr, nullptr, nullptr, y2, s2, q2, g2, be2,
        w3, b3, y3, p3);
    reduce_stats<<<128, 256>>>(p3, s3, q3, 4096, 2);
    // 6) BN3 + relu + max over nsample
    final_kernel<<<NB * NPOINT, 128>>>(y3, s3, q3, g3, be3, out);
}

// round 5
// speedup vs baseline: 2.0368x; 2.0368x over previous
#include <cuda_runtime.h>
#include <cstdint>

typedef unsigned long long ull;

// Problem constants
constexpr int NB = 16, NN = 8192, NPOINT = 1024, NSAMPLE = 32;
constexpr int M_TOTAL = NB * NPOINT * NSAMPLE;       // 524288 positions
constexpr float INV_N = 1.0f / (float)M_TOTAL;       // 2^-19, exact
constexpr int NEWXYZ_ELEMS = NB * NPOINT * 3;        // 49152

// -------- scratch (device globals; no allocation allowed) --------
__device__ float g_y1[(size_t)M_TOTAL * 64];
__device__ float g_y2[(size_t)M_TOTAL * 64];
__device__ float g_y3[(size_t)M_TOTAL * 128];
__device__ int   g_idx[M_TOTAL];
__device__ float g_part1[4096 * 128];
__device__ float g_part2[4096 * 128];
__device__ float g_part3[8192 * 128];
__device__ float g_sc1[64],  g_sh1[64];
__device__ float g_sc2[64],  g_sh2[64];
__device__ float g_sc3[128], g_sh3[128];
__device__ int   g_tick[4];

// ---------------- helpers ----------------
__device__ __forceinline__ void ffma2(ull& d, ull a, ull b) {
    asm("fma.rn.f32x2 %0, %1, %2, %0;" : "+l"(d) : "l"(a), "l"(b));
}
__device__ __forceinline__ float hadd2(ull v) {
    float lo, hi;
    asm("mov.b64 {%0, %1}, %2;" : "=f"(lo), "=f"(hi) : "l"(v));
    return lo + hi;
}
// TF32 rounding (round-to-nearest-away), matching the tensor-core input path.
__device__ __forceinline__ float to_tf32(float x) {
    unsigned u;
    asm("cvt.rna.tf32.f32 %0, %1;" : "=r"(u) : "f"(x));
    return __uint_as_float(u);
}
// XLA-GPU contracted squared distance: fma chain in axis order.
__device__ __forceinline__ float sqdist3(float dx, float dy, float dz) {
    return fmaf(dz, dz, fmaf(dy, dy, __fmul_rn(dx, dx)));
}

// ---------------- 0) init (reset ticket counters each replay) ----------------
__global__ void init_kernel() {
    if (threadIdx.x < 4) g_tick[threadIdx.x] = 0;
}

// ---------------- 1) farthest point sampling ----------------
// One block per batch; 512 threads x 16 points, state in registers.
__global__ void __launch_bounds__(512) fps_kernel(const float* __restrict__ xyz,
                                                  float* __restrict__ newxyz) {
    const int b = blockIdx.x, tid = threadIdx.x;
    const float* X = xyz + (size_t)b * NN * 3;
    float px[16], py[16], pz[16], dd[16];
#pragma unroll
    for (int j = 0; j < 16; j++) {
        int p = tid * 16 + j;
        px[j] = X[p * 3 + 0]; py[j] = X[p * 3 + 1]; pz[j] = X[p * 3 + 2];
        dd[j] = 1e10f;
    }
    __shared__ float sc[3];
    __shared__ int sF;
    __shared__ int swv[16];
    __shared__ int swi[16];
    if (tid == 0) { sc[0] = px[0]; sc[1] = py[0]; sc[2] = pz[0]; }
    __syncthreads();

    float* outb = newxyz + (size_t)b * NPOINT * 3;
    const int lane = tid & 31, wid = tid >> 5;

    for (int it = 0; it < NPOINT; ++it) {
        if (tid == 0) {
            outb[it * 3 + 0] = sc[0];
            outb[it * 3 + 1] = sc[1];
            outb[it * 3 + 2] = sc[2];
        }
        const float cx = sc[0], cy = sc[1], cz = sc[2];
        float best = -1.0f; int bi = 0;
#pragma unroll
        for (int j = 0; j < 16; j++) {
            float dx = __fsub_rn(px[j], cx);
            float dy = __fsub_rn(py[j], cy);
            float dz = __fsub_rn(pz[j], cz);
            float d = sqdist3(dx, dy, dz);
            float nd = fminf(dd[j], d);
            dd[j] = nd;
            if (nd > best) { best = nd; bi = tid * 16 + j; }
        }
        // warp argmax: nonneg float bits compare as ints; ballot for min-index tie
        int vb = __float_as_int(best);
        int wmax = __reduce_max_sync(0xffffffffu, vb);
        unsigned msk = __ballot_sync(0xffffffffu, vb == wmax);
        int ldr = __ffs(msk) - 1;
        int widx = __shfl_sync(0xffffffffu, bi, ldr);
        if (lane == 0) { swv[wid] = wmax; swi[wid] = widx; }
        __syncthreads();
        if (wid == 0 && lane < 16) {
            int v2 = swv[lane], i2 = swi[lane];
            int m2 = __reduce_max_sync(0xffffu, v2);
            unsigned mk2 = __ballot_sync(0xffffu, v2 == m2);
            int l2 = __ffs(mk2) - 1;
            int fi = __shfl_sync(0xffffu, i2, l2);
            if (lane == 0) sF = fi;
        }
        __syncthreads();
        int f = sF;
        if ((f >> 4) == tid) {
            int j = f & 15;
            sc[0] = px[j]; sc[1] = py[j]; sc[2] = pz[j];
        }
        __syncthreads();
    }
}

// ---------------- 2) ball query ----------------
__global__ void __launch_bounds__(256) ball_kernel(const float* __restrict__ xyz,
                                                   const float* __restrict__ newxyz,
                                                   int* __restrict__ gidx) {
    const int gwarp = (blockIdx.x * blockDim.x + threadIdx.x) >> 5;
    const int lane = threadIdx.x & 31;
    if (gwarp >= NB * NPOINT) return;
    const int b = gwarp >> 10;
    const float R2 = (float)(0.2 * 0.2);

    const float cx = newxyz[gwarp * 3 + 0];
    const float cy = newxyz[gwarp * 3 + 1];
    const float cz = newxyz[gwarp * 3 + 2];
    const float* X = xyz + (size_t)b * NN * 3;
    int* out = gidx + (size_t)gwarp * NSAMPLE;

    int cnt = 0;
    int first = NN - 1;
    for (int base = 0; base < NN; base += 32) {
        int j = base + lane;
        float dx = __fsub_rn(cx, X[j * 3 + 0]);
        float dy = __fsub_rn(cy, X[j * 3 + 1]);
        float dz = __fsub_rn(cz, X[j * 3 + 2]);
        float sq = sqdist3(dx, dy, dz);
        bool in = !(sq > R2);
        unsigned mask = __ballot_sync(0xffffffffu, in);
        if (mask) {
            if (cnt == 0) first = base + __ffs(mask) - 1;
            if (in) {
                int slot = cnt + __popc(mask & ((1u << lane) - 1u));
                if (slot < NSAMPLE) out[slot] = j;
            }
            cnt += __popc(mask);
            if (cnt >= NSAMPLE) break;
        }
    }
    if (cnt < NSAMPLE && lane >= cnt) out[lane] = first;
}

// ---------------- 3) fused GEMM + last-block BN-stats reduction ----------------
// STRIDE: smem row stride (floats), odd*2 so bank-pair (stride/2*m + c/2) mod 16
// spans all 16 pairs -> conflict-free. CEFF: channel loop bound (mult of 4).
// MODE 1: gather 67ch -> y1.  MODE 2: y1->y2.  MODE 3: y2->y3 (obase = blk&1).
template <int STRIDE, int CEFF, int MODE>
__global__ void __launch_bounds__(256) gemm_kernel(
    const float* __restrict__ xyz, const float* __restrict__ points,
    const float* __restrict__ newxyz, const int* __restrict__ gidx,
    const float* __restrict__ yin,
    const float* __restrict__ scin, const float* __restrict__ shin,
    const float* __restrict__ pg, const float* __restrict__ pbe,
    const float* __restrict__ W, const float* __restrict__ bias,
    float* __restrict__ yout, float* __restrict__ part,
    float* __restrict__ scout, float* __restrict__ shout,
    int* __restrict__ tick) {
    constexpr int CIN = (MODE == 1) ? 67 : 64;
    constexpr int OSTRIDE = (MODE == 3) ? 128 : 64;
    extern __shared__ float smem[];
    float* Ws = smem;                   // [64][STRIDE]
    float* Xs = smem + 64 * STRIDE;     // [128][STRIDE]
    __shared__ int sIdx[128];
    __shared__ float sNew[4][3];
    __shared__ float sSc[64], sSh[64];
    __shared__ int sLast;

    const int tid = threadIdx.x;
    int m_tile, obase;
    if (MODE == 3) { m_tile = blockIdx.x >> 1; obase = (blockIdx.x & 1) << 6; }
    else           { m_tile = blockIdx.x;      obase = 0; }
    const int m0 = m_tile * 128;

    for (int e = tid; e < 64 * STRIDE; e += 256) {
        int o = e / STRIDE, c = e - o * STRIDE;
        Ws[e] = (c < CIN) ? to_tf32(W[(obase + o) * CIN + c]) : 0.0f;
    }

    if (MODE == 1) {
        if (tid < 128) sIdx[tid] = gidx[m0 + tid];
        if (tid < 12) ((float*)sNew)[tid] = newxyz[(m0 >> 5) * 3 + tid];
    } else {
        if (tid < 64) { sSc[tid] = scin[tid]; sSh[tid] = shin[tid]; }
    }
    __syncthreads();

    if (MODE == 1) {
        const int bb = m0 >> 15;
        const float* Xb = xyz + (size_t)bb * NN * 3;
        const float* Pb = points + (size_t)bb * NN * 64;
        for (int e = tid; e < 128 * STRIDE; e += 256) {
            int m = e / STRIDE, c = e - m * STRIDE;
            int gi = sIdx[m];
            float v;
            if (c < 3)       v = __fsub_rn(Xb[gi * 3 + c], sNew[m >> 5][c]);
            else if (c < 67) v = Pb[(size_t)gi * 64 + (c - 3)];
            else             v = 0.0f;
            Xs[m * STRIDE + c] = (c < 67) ? to_tf32(v) : 0.0f;
        }
    } else {
        for (int e = tid; e < 128 * 16; e += 256) {
            int m = e >> 4, cq = e & 15, c = cq * 4;
            float4 v = *reinterpret_cast<const float4*>(&yin[((size_t)(m0 + m)) * 64 + c]);
            v.x = to_tf32(fmaxf(fmaf(v.x, sSc[c + 0], sSh[c + 0]), 0.0f));
            v.y = to_tf32(fmaxf(fmaf(v.y, sSc[c + 1], sSh[c + 1]), 0.0f));
            v.z = to_tf32(fmaxf(fmaf(v.z, sSc[c + 2], sSh[c + 2]), 0.0f));
            v.w = to_tf32(fmaxf(fmaf(v.w, sSc[c + 3], sSh[c + 3]), 0.0f));
            float* p = &Xs[m * STRIDE + c];
            *reinterpret_cast<float2*>(p) = make_float2(v.x, v.y);
            *reinterpret_cast<float2*>(p + 2) = make_float2(v.z, v.w);
        }
    }
    __syncthreads();

    const int mg = tid & 15, og = tid >> 4;
    ull acc[32];
#pragma unroll
    for (int i = 0; i < 32; i++) acc[i] = 0ULL;

    for (int c = 0; c < CEFF; c += 4) {
        ull wv[8];
#pragma unroll
        for (int j = 0; j < 4; j++) {
            const ull* wp = reinterpret_cast<const ull*>(&Ws[(og * 4 + j) * STRIDE + c]);
            wv[2 * j] = wp[0]; wv[2 * j + 1] = wp[1];
        }
#pragma unroll
        for (int i = 0; i < 8; i++) {
            const ull* xp = reinterpret_cast<const ull*>(&Xs[(mg + 16 * i) * STRIDE + c]);
            ull x0 = xp[0], x1 = xp[1];
#pragma unroll
            for (int j = 0; j < 4; j++) {
                ffma2(acc[i * 4 + j], x0, wv[2 * j]);
                ffma2(acc[i * 4 + j], x1, wv[2 * j + 1]);
            }
        }
    }

    float bj[4];
#pragma unroll
    for (int j = 0; j < 4; j++) bj[j] = bias[obase + og * 4 + j];
    float sums[4] = {0, 0, 0, 0}, ssqs[4] = {0, 0, 0, 0};
#pragma unroll
    for (int i = 0; i < 8; i++) {
        float y[4];
#pragma unroll
        for (int j = 0; j < 4; j++) {
            float v = hadd2(acc[i * 4 + j]) + bj[j];
            y[j] = v;
            sums[j] += v;
            ssqs[j] += v * v;
        }
        *reinterpret_cast<float4*>(
            &yout[((size_t)(m0 + mg + 16 * i)) * OSTRIDE + obase + og * 4]) =
            make_float4(y[0], y[1], y[2], y[3]);
    }
#pragma unroll
    for (int off = 8; off; off >>= 1) {
#pragma unroll
        for (int j = 0; j < 4; j++) {
            sums[j] += __shfl_down_sync(0xffffffffu, sums[j], off);
            ssqs[j] += __shfl_down_sync(0xffffffffu, ssqs[j], off);
        }
    }
    if (mg == 0) {
#pragma unroll
        for (int j = 0; j < 4; j++) {
            part[blockIdx.x * 128 + og * 4 + j] = sums[j];
            part[blockIdx.x * 128 + 64 + og * 4 + j] = ssqs[j];
        }
    }

    // ---- last-block BN stats reduction (deterministic: fixed data, fixed order) ----
    __threadfence();
    __syncthreads();
    if (tid == 0) sLast = (atomicAdd(tick, 1) == (int)gridDim.x - 1);
    __syncthreads();
    if (!sLast) return;
    __threadfence();

    if (MODE != 3) {
        // 4096 rows x (64 sums + 64 ssqs); 256 thr = 4 groups x 64 ch
        const int g = tid >> 6, ch = tid & 63;
        float s = 0.0f, ss = 0.0f;
        for (int r = g; r < 4096; r += 4) {
            s += part[r * 128 + ch];
            ss += part[r * 128 + 64 + ch];
        }
        __shared__ float redS[4][64], redQ[4][64];
        redS[g][ch] = s; redQ[g][ch] = ss;
        __syncthreads();
        if (tid < 64) {
            float S = redS[0][tid] + redS[1][tid] + redS[2][tid] + redS[3][tid];
            float Q = redQ[0][tid] + redQ[1][tid] + redQ[2][tid] + redQ[3][tid];
            float mean = S * INV_N;
            float var = Q * INV_N - mean * mean;
            float inv = rsqrtf(var + 1e-5f);
            float scv = pg[tid] * inv;
            scout[tid] = scv;
            shout[tid] = pbe[tid] - mean * scv;
        }
    } else {
        // 8192 rows; channel ch: parity p=ch>>6 rows, local lc=ch&63
        const int g = tid >> 7, ch = tid & 127;
        const int p = ch >> 6, lc = ch & 63;
        float s = 0.0f, ss = 0.0f;
        for (int i = g; i < 4096; i += 2) {
            int r = 2 * i + p;
            s += part[r * 128 + lc];
            ss += part[r * 128 + 64 + lc];
        }
        __shared__ float redS3[2][128], redQ3[2][128];
        redS3[g][ch] = s; redQ3[g][ch] = ss;
        __syncthreads();
        if (tid < 128) {
            float S = redS3[0][tid] + redS3[1][tid];
            float Q = redQ3[0][tid] + redQ3[1][tid];
            float mean = S * INV_N;
            float var = Q * INV_N - mean * mean;
            float inv = rsqrtf(var + 1e-5f);
            float scv = pg[tid] * inv;
            scout[tid] = scv;
            shout[tid] = pbe[tid] - mean * scv;
        }
    }
}

// ---------------- 5) BN3 + ReLU + max over k ----------------
__global__ void __launch_bounds__(128) final_kernel(const float* __restrict__ y3,
                                                    const float* __restrict__ sc3,
                                                    const float* __restrict__ sh3,
                                                    float* __restrict__ out) {
    const int q = blockIdx.x;      // b*1024 + s
    const int o = threadIdx.x;     // channel 0..127
    float scv = sc3[o], sh = sh3[o];
    const float* base = y3 + (size_t)q * NSAMPLE * 128;
    float mx = -1e30f;
#pragma unroll 8
    for (int k = 0; k < NSAMPLE; k++) {
        float v = base[k * 128 + o];
        v = fmaxf(fmaf(v, scv, sh), 0.0f);
        mx = fmaxf(mx, v);
    }
    const int b = q >> 10, si = q & 1023;
    out[NEWXYZ_ELEMS + ((size_t)(b * 128 + o)) * 1024 + si] = mx;
}

// ---------------- launch ----------------
extern "C" void kernel_launch(void* const* d_in, const int* in_sizes, int n_in,
                              void* d_out, int out_size) {
    const float* xyz    = (const float*)d_in[0];
    const float* points = (const float*)d_in[1];
    const float* w1 = (const float*)d_in[2];
    const float* b1 = (const float*)d_in[3];
    const float* g1 = (const float*)d_in[4];
    const float* be1 = (const float*)d_in[5];
    const float* w2 = (const float*)d_in[6];
    const float* b2 = (const float*)d_in[7];
    const float* g2 = (const float*)d_in[8];
    const float* be2 = (const float*)d_in[9];
    const float* w3 = (const float*)d_in[10];
    const float* b3 = (const float*)d_in[11];
    const float* g3 = (const float*)d_in[12];
    const float* be3 = (const float*)d_in[13];
    float* out = (float*)d_out;

    float *y1, *y2, *y3, *p1, *p2, *p3;
    float *sc1, *sh1, *sc2, *sh2, *sc3, *sh3;
    int *idx, *tick;
    cudaGetSymbolAddress((void**)&y1, g_y1);
    cudaGetSymbolAddress((void**)&y2, g_y2);
    cudaGetSymbolAddress((void**)&y3, g_y3);
    cudaGetSymbolAddress((void**)&idx, g_idx);
    cudaGetSymbolAddress((void**)&p1, g_part1);
    cudaGetSymbolAddress((void**)&p2, g_part2);
    cudaGetSymbolAddress((void**)&p3, g_part3);
    cudaGetSymbolAddress((void**)&sc1, g_sc1);
    cudaGetSymbolAddress((void**)&sh1, g_sh1);
    cudaGetSymbolAddress((void**)&sc2, g_sc2);
    cudaGetSymbolAddress((void**)&sh2, g_sh2);
    cudaGetSymbolAddress((void**)&sc3, g_sc3);
    cudaGetSymbolAddress((void**)&sh3, g_sh3);
    cudaGetSymbolAddress((void**)&tick, g_tick);

    const int smem1 = (64 + 128) * 74 * 4;  // 56832
    const int smem2 = (64 + 128) * 66 * 4;  // 50688
    cudaFuncSetAttribute(gemm_kernel<74, 68, 1>, cudaFuncAttributeMaxDynamicSharedMemorySize, smem1);
    cudaFuncSetAttribute(gemm_kernel<66, 64, 2>, cudaFuncAttributeMaxDynamicSharedMemorySize, smem2);
    cudaFuncSetAttribute(gemm_kernel<66, 64, 3>, cudaFuncAttributeMaxDynamicSharedMemorySize, smem2);

    // 0) reset ticket counters (required for deterministic graph replay)
    init_kernel<<<1, 32>>>();
    // 1) FPS -> new_xyz (first 49152 elems of out)
    fps_kernel<<<NB, 512>>>(xyz, out);
    // 2) ball query -> g_idx
    ball_kernel<<<(NB * NPOINT * 32) / 256, 256>>>(xyz, out, idx);
    // 3) layer1 (gather 67ch -> 64); last block emits BN1 coefs
    gemm_kernel<74, 68, 1><<<M_TOTAL / 128, 256, smem1>>>(
        xyz, points, out, idx, nullptr, nullptr, nullptr, g1, be1,
        w1, b1, y1, p1, sc1, sh1, &tick[0]);
    // 4) layer2 (BN1+relu fused on load); last block emits BN2 coefs
    gemm_kernel<66, 64, 2><<<M_TOTAL / 128, 256, smem2>>>(
        nullptr, nullptr, nullptr, nullptr, y1, sc1, sh1, g2, be2,
        w2, b2, y2, p2, sc2, sh2, &tick[1]);
    // 5) layer3 (BN2+relu fused on load, O=128 split); last block emits BN3 coefs
    gemm_kernel<66, 64, 3><<<2 * (M_TOTAL / 128), 256, smem2>>>(
        nullptr, nullptr, nullptr, nullptr, y2, sc2, sh2, g3, be3,
        w3, b3, y3, p3, sc3, sh3, &tick[2]);
    // 6) BN3 + relu + max over nsample
    final_kernel<<<NB * NPOINT, 128>>>(y3, sc3, sh3, out);
}

// round 8
// speedup vs baseline: 2.6012x; 1.2771x over previous
#include <cuda_runtime.h>
#include <cstdint>

typedef unsigned long long ull;

// Problem constants
constexpr int NB = 16, NN = 8192, NPOINT = 1024, NSAMPLE = 32;
constexpr int M_TOTAL = NB * NPOINT * NSAMPLE;       // 524288 positions
constexpr float INV_N = 1.0f / (float)M_TOTAL;       // 2^-19, exact
constexpr int NEWXYZ_ELEMS = NB * NPOINT * 3;        // 49152

// -------- scratch (device globals; no allocation allowed) --------
__device__ float g_y1[(size_t)M_TOTAL * 64];
__device__ float g_y2[(size_t)M_TOTAL * 64];
__device__ float g_y3[(size_t)M_TOTAL * 128];
__device__ int   g_idx[M_TOTAL];
__device__ float g_part1[4096 * 128];
__device__ float g_part2[4096 * 128];
__device__ float g_part3[8192 * 128];
__device__ float g_sc1[64],  g_sh1[64];
__device__ float g_sc2[64],  g_sh2[64];
__device__ float g_sc3[128], g_sh3[128];
__device__ int   g_tick[4];

// ---------------- helpers ----------------
__device__ __forceinline__ float to_tf32(float x) {
    unsigned u;
    asm("cvt.rna.tf32.f32 %0, %1;" : "=r"(u) : "f"(x));
    return __uint_as_float(u);
}
__device__ __forceinline__ float sqdist3(float dx, float dy, float dz) {
    return fmaf(dz, dz, fmaf(dy, dy, __fmul_rn(dx, dx)));
}
// m16n8k8 tf32 HMMA (PTX-portable on compute_103; runs on tensor pipes)
__device__ __forceinline__ void mma16n8k8(float* d, const uint32_t* a,
                                          const uint32_t* b) {
    asm volatile(
        "mma.sync.aligned.m16n8k8.row.col.f32.tf32.tf32.f32 "
        "{%0,%1,%2,%3}, {%4,%5,%6,%7}, {%8,%9}, {%0,%1,%2,%3};"
        : "+f"(d[0]), "+f"(d[1]), "+f"(d[2]), "+f"(d[3])
        : "r"(a[0]), "r"(a[1]), "r"(a[2]), "r"(a[3]), "r"(b[0]), "r"(b[1]));
}

// ---------------- 0) init (reset ticket counters each replay) ----------------
__global__ void init_kernel() {
    if (threadIdx.x < 4) g_tick[threadIdx.x] = 0;
}

// ---------------- 1) farthest point sampling ----------------
__global__ void __launch_bounds__(512) fps_kernel(const float* __restrict__ xyz,
                                                  float* __restrict__ newxyz) {
    const int b = blockIdx.x, tid = threadIdx.x;
    const float* X = xyz + (size_t)b * NN * 3;
    float px[16], py[16], pz[16], dd[16];
#pragma unroll
    for (int j = 0; j < 16; j++) {
        int p = tid * 16 + j;
        px[j] = X[p * 3 + 0]; py[j] = X[p * 3 + 1]; pz[j] = X[p * 3 + 2];
        dd[j] = 1e10f;
    }
    __shared__ float sc[3];
    __shared__ int sF;
    __shared__ int swv[16];
    __shared__ int swi[16];
    if (tid == 0) { sc[0] = px[0]; sc[1] = py[0]; sc[2] = pz[0]; }
    __syncthreads();

    float* outb = newxyz + (size_t)b * NPOINT * 3;
    const int lane = tid & 31, wid = tid >> 5;

    for (int it = 0; it < NPOINT; ++it) {
        if (tid == 0) {
            outb[it * 3 + 0] = sc[0];
            outb[it * 3 + 1] = sc[1];
            outb[it * 3 + 2] = sc[2];
        }
        const float cx = sc[0], cy = sc[1], cz = sc[2];
        float best = -1.0f; int bi = 0;
#pragma unroll
        for (int j = 0; j < 16; j++) {
            float dx = __fsub_rn(px[j], cx);
            float dy = __fsub_rn(py[j], cy);
            float dz = __fsub_rn(pz[j], cz);
            float d = sqdist3(dx, dy, dz);
            float nd = fminf(dd[j], d);
            dd[j] = nd;
            if (nd > best) { best = nd; bi = tid * 16 + j; }
        }
        int vb = __float_as_int(best);
        int wmax = __reduce_max_sync(0xffffffffu, vb);
        unsigned msk = __ballot_sync(0xffffffffu, vb == wmax);
        int ldr = __ffs(msk) - 1;
        int widx = __shfl_sync(0xffffffffu, bi, ldr);
        if (lane == 0) { swv[wid] = wmax; swi[wid] = widx; }
        __syncthreads();
        if (wid == 0 && lane < 16) {
            int v2 = swv[lane], i2 = swi[lane];
            int m2 = __reduce_max_sync(0xffffu, v2);
            unsigned mk2 = __ballot_sync(0xffffu, v2 == m2);
            int l2 = __ffs(mk2) - 1;
            int fi = __shfl_sync(0xffffu, i2, l2);
            if (lane == 0) sF = fi;
        }
        __syncthreads();
        int f = sF;
        if ((f >> 4) == tid) {
            int j = f & 15;
            sc[0] = px[j]; sc[1] = py[j]; sc[2] = pz[j];
        }
        __syncthreads();
    }
}

// ---------------- 2) ball query ----------------
__global__ void __launch_bounds__(256) ball_kernel(const float* __restrict__ xyz,
                                                   const float* __restrict__ newxyz,
                                                   int* __restrict__ gidx) {
    const int gwarp = (blockIdx.x * blockDim.x + threadIdx.x) >> 5;
    const int lane = threadIdx.x & 31;
    if (gwarp >= NB * NPOINT) return;
    const int b = gwarp >> 10;
    const float R2 = (float)(0.2 * 0.2);

    const float cx = newxyz[gwarp * 3 + 0];
    const float cy = newxyz[gwarp * 3 + 1];
    const float cz = newxyz[gwarp * 3 + 2];
    const float* X = xyz + (size_t)b * NN * 3;
    int* out = gidx + (size_t)gwarp * NSAMPLE;

    int cnt = 0;
    int first = NN - 1;
    for (int base = 0; base < NN; base += 32) {
        int j = base + lane;
        float dx = __fsub_rn(cx, X[j * 3 + 0]);
        float dy = __fsub_rn(cy, X[j * 3 + 1]);
        float dz = __fsub_rn(cz, X[j * 3 + 2]);
        float sq = sqdist3(dx, dy, dz);
        bool in = !(sq > R2);
        unsigned mask = __ballot_sync(0xffffffffu, in);
        if (mask) {
            if (cnt == 0) first = base + __ffs(mask) - 1;
            if (in) {
                int slot = cnt + __popc(mask & ((1u << lane) - 1u));
                if (slot < NSAMPLE) out[slot] = j;
            }
            cnt += __popc(mask);
            if (cnt >= NSAMPLE) break;
        }
    }
    if (cnt < NSAMPLE && lane >= cnt) out[lane] = first;
}

// ---------------- 3) HMMA tf32 GEMM per layer (+ BN fused) ----------------
// Block = 128 threads (4 warps), tile = 128 positions x 64 outputs.
// As[128][STR], Bs[64][STR] in smem, STR = KP+4 (conflict-free fragments).
// Warp w: rows w*32..w*32+31; 2 m-tiles x 8 n-tiles of m16n8k8 tf32 MMA.
// MODE 1: gather grouped features (67 ch).  MODE 2: y1->y2.  MODE 3: y2->y3.
template <int MODE>
__global__ void __launch_bounds__(128) mma_kernel(
    const float* __restrict__ xyz, const float* __restrict__ points,
    const float* __restrict__ newxyz, const int* __restrict__ gidx,
    const float* __restrict__ yin,
    const float* __restrict__ scin, const float* __restrict__ shin,
    const float* __restrict__ pg, const float* __restrict__ pbe,
    const float* __restrict__ W, const float* __restrict__ bias,
    float* __restrict__ yout, float* __restrict__ part,
    float* __restrict__ scout, float* __restrict__ shout,
    int* __restrict__ tick) {
    constexpr int CIN = (MODE == 1) ? 67 : 64;
    constexpr int KP  = (MODE == 1) ? 72 : 64;   // padded K (mult of 8)
    constexpr int STR = KP + 4;                   // 76 / 68 floats
    constexpr int NK  = KP / 8;                   // 9 / 8
    constexpr int OSTRIDE = (MODE == 3) ? 128 : 64;

    extern __shared__ float sm[];
    float* As = sm;                // [128][STR]
    float* Bs = sm + 128 * STR;    // [64][STR]
    __shared__ float sSc[64], sSh[64], sBias[64];
    __shared__ float sNew[4][3];
    __shared__ float redS[2][64], redQ[2][64];
    __shared__ int sLast;

    const int tid = threadIdx.x;
    const int lane = tid & 31, w = tid >> 5;
    int m_tile, obase;
    if (MODE == 3) { m_tile = blockIdx.x >> 1; obase = (blockIdx.x & 1) << 6; }
    else           { m_tile = blockIdx.x;      obase = 0; }
    const int m0 = m_tile * 128;

    if (tid < 64) sBias[tid] = bias[obase + tid];
    if (MODE == 1) {
        if (tid < 12) ((float*)sNew)[tid] = newxyz[(m0 >> 5) * 3 + tid];
    } else {
        if (tid >= 64) { sSc[tid - 64] = scin[tid - 64]; sSh[tid - 64] = shin[tid - 64]; }
    }
    __syncthreads();

    // ---- B (weights) -> smem, tf32-rounded, zero padded ----
    for (int e = tid; e < 64 * KP; e += 128) {
        int o = e / KP, c = e - o * KP;
        Bs[o * STR + c] = (c < CIN) ? to_tf32(W[(obase + o) * CIN + c]) : 0.0f;
    }

    // ---- A (activations) -> smem (one row per thread) ----
    {
        const int m = tid;
        float* Arow = As + m * STR;
        if (MODE == 1) {
            const int bb = m0 >> 15;
            const int gi = gidx[m0 + m];
            const float* Xb = xyz + ((size_t)bb * NN + gi) * 3;
            const float* Pb = points + ((size_t)bb * NN + gi) * 64;
            float pe[64];
#pragma unroll
            for (int j = 0; j < 16; j++) {
                float4 t = reinterpret_cast<const float4*>(Pb)[j];
                pe[4 * j + 0] = t.x; pe[4 * j + 1] = t.y;
                pe[4 * j + 2] = t.z; pe[4 * j + 3] = t.w;
            }
            Arow[0] = to_tf32(__fsub_rn(Xb[0], sNew[m >> 5][0]));
            Arow[1] = to_tf32(__fsub_rn(Xb[1], sNew[m >> 5][1]));
            Arow[2] = to_tf32(__fsub_rn(Xb[2], sNew[m >> 5][2]));
#pragma unroll
            for (int c = 0; c < 64; c++) Arow[3 + c] = to_tf32(pe[c]);
#pragma unroll
            for (int c = CIN; c < KP; c++) Arow[c] = 0.0f;
        } else {
            const float4* yrow =
                reinterpret_cast<const float4*>(&yin[(size_t)(m0 + m) * 64]);
#pragma unroll
            for (int q = 0; q < 16; q++) {
                float4 v = yrow[q];
                int c = q * 4;
                v.x = to_tf32(fmaxf(fmaf(v.x, sSc[c + 0], sSh[c + 0]), 0.0f));
                v.y = to_tf32(fmaxf(fmaf(v.y, sSc[c + 1], sSh[c + 1]), 0.0f));
                v.z = to_tf32(fmaxf(fmaf(v.z, sSc[c + 2], sSh[c + 2]), 0.0f));
                v.w = to_tf32(fmaxf(fmaf(v.w, sSc[c + 3], sSh[c + 3]), 0.0f));
                *reinterpret_cast<float4*>(Arow + c) = v;
            }
        }
    }
    __syncthreads();

    // ---- MMA mainloop ----
    const int r = lane >> 2, cq = lane & 3;
    float acc[16][4];
#pragma unroll
    for (int i = 0; i < 16; i++) {
        acc[i][0] = 0.0f; acc[i][1] = 0.0f; acc[i][2] = 0.0f; acc[i][3] = 0.0f;
    }
#pragma unroll
    for (int ks = 0; ks < NK; ks++) {
        const int k = ks * 8;
        uint32_t a[2][4];
#pragma unroll
        for (int mt = 0; mt < 2; mt++) {
            const float* p = As + (w * 32 + mt * 16 + r) * STR + k + cq;
            a[mt][0] = __float_as_uint(p[0]);
            a[mt][1] = __float_as_uint(p[8 * STR]);
            a[mt][2] = __float_as_uint(p[4]);
            a[mt][3] = __float_as_uint(p[8 * STR + 4]);
        }
#pragma unroll
        for (int nt = 0; nt < 8; nt++) {
            const float* q = Bs + (nt * 8 + r) * STR + k + cq;
            uint32_t b[2];
            b[0] = __float_as_uint(q[0]);
            b[1] = __float_as_uint(q[4]);
            mma16n8k8(acc[nt], a[0], b);
            mma16n8k8(acc[8 + nt], a[1], b);
        }
    }
    __syncthreads();   // A/B smem dead; reuse as ys[128][65]

    // ---- epilogue: bias add, scatter to ys[m][o] ----
    float* ys = sm;
#pragma unroll
    for (int mt = 0; mt < 2; mt++) {
#pragma unroll
        for (int nt = 0; nt < 8; nt++) {
            const int row = w * 32 + mt * 16 + r;
            const int col = nt * 8 + 2 * cq;
            const float* c = acc[mt * 8 + nt];
            ys[row * 65 + col]           = c[0] + sBias[col];
            ys[row * 65 + col + 1]       = c[1] + sBias[col + 1];
            ys[(row + 8) * 65 + col]     = c[2] + sBias[col];
            ys[(row + 8) * 65 + col + 1] = c[3] + sBias[col + 1];
        }
    }
    __syncthreads();

    // block stats (deterministic order)
    {
        const int o = tid & 63, h = tid >> 6;
        float s = 0.0f, ss = 0.0f;
#pragma unroll 8
        for (int i = 0; i < 64; i++) {
            float v = ys[(h * 64 + i) * 65 + o];
            s += v; ss += v * v;
        }
        redS[h][o] = s; redQ[h][o] = ss;
    }
    __syncthreads();
    if (tid < 64) {
        part[blockIdx.x * 128 + tid] = redS[0][tid] + redS[1][tid];
        part[blockIdx.x * 128 + 64 + tid] = redQ[0][tid] + redQ[1][tid];
    }
    // coalesced y write
    for (int e = tid; e < 8192; e += 128) {
        int mm = e >> 6, o = e & 63;
        yout[(size_t)(m0 + mm) * OSTRIDE + obase + o] = ys[mm * 65 + o];
    }

    // ---- last-block BN stats reduction (deterministic) ----
    __threadfence();
    __syncthreads();
    if (tid == 0) sLast = (atomicAdd(tick, 1) == (int)gridDim.x - 1);
    __syncthreads();
    if (!sLast) return;
    __threadfence();

    if (MODE != 3) {
        const int h = tid >> 6, ch = tid & 63;
        float s = 0.0f, ss = 0.0f;
        for (int rr = h; rr < 4096; rr += 2) {
            s += part[rr * 128 + ch];
            ss += part[rr * 128 + 64 + ch];
        }
        redS[h][ch] = s; redQ[h][ch] = ss;
        __syncthreads();
        if (tid < 64) {
            float S = redS[0][tid] + redS[1][tid];
            float Q = redQ[0][tid] + redQ[1][tid];
            float mean = S * INV_N;
            float var = Q * INV_N - mean * mean;
            float inv = rsqrtf(var + 1e-5f);
            float scv = pg[tid] * inv;
            scout[tid] = scv;
            shout[tid] = pbe[tid] - mean * scv;
        }
    } else {
        const int ch = tid, p = ch >> 6, lc = ch & 63;
        float s = 0.0f, ss = 0.0f;
        for (int i = 0; i < 4096; i++) {
            int rr = 2 * i + p;
            s += part[rr * 128 + lc];
            ss += part[rr * 128 + 64 + lc];
        }
        float mean = s * INV_N;
        float var = ss * INV_N - mean * mean;
        float inv = rsqrtf(var + 1e-5f);
        float scv = pg[ch] * inv;
        scout[ch] = scv;
        shout[ch] = pbe[ch] - mean * scv;
    }
}

// ---------------- 5) BN3 + ReLU + max over k ----------------
__global__ void __launch_bounds__(128) final_kernel(const float* __restrict__ y3,
                                                    const float* __restrict__ sc3,
                                                    const float* __restrict__ sh3,
                                                    float* __restrict__ out) {
    const int q = blockIdx.x;      // b*1024 + s
    const int o = threadIdx.x;     // channel 0..127
    float scv = sc3[o], sh = sh3[o];
    const float* base = y3 + (size_t)q * NSAMPLE * 128;
    float mx = -1e30f;
#pragma unroll 8
    for (int k = 0; k < NSAMPLE; k++) {
        float v = base[k * 128 + o];
        v = fmaxf(fmaf(v, scv, sh), 0.0f);
        mx = fmaxf(mx, v);
    }
    const int b = q >> 10, si = q & 1023;
    out[NEWXYZ_ELEMS + ((size_t)(b * 128 + o)) * 1024 + si] = mx;
}

// ---------------- launch ----------------
extern "C" void kernel_launch(void* const* d_in, const int* in_sizes, int n_in,
                              void* d_out, int out_size) {
    const float* xyz    = (const float*)d_in[0];
    const float* points = (const float*)d_in[1];
    const float* w1 = (const float*)d_in[2];
    const float* b1 = (const float*)d_in[3];
    const float* g1 = (const float*)d_in[4];
    const float* be1 = (const float*)d_in[5];
    const float* w2 = (const float*)d_in[6];
    const float* b2 = (const float*)d_in[7];
    const float* g2 = (const float*)d_in[8];
    const float* be2 = (const float*)d_in[9];
    const float* w3 = (const float*)d_in[10];
    const float* b3 = (const float*)d_in[11];
    const float* g3 = (const float*)d_in[12];
    const float* be3 = (const float*)d_in[13];
    float* out = (float*)d_out;

    float *y1, *y2, *y3, *p1, *p2, *p3;
    float *sc1, *sh1, *sc2, *sh2, *sc3, *sh3;
    int *idx, *tick;
    cudaGetSymbolAddress((void**)&y1, g_y1);
    cudaGetSymbolAddress((void**)&y2, g_y2);
    cudaGetSymbolAddress((void**)&y3, g_y3);
    cudaGetSymbolAddress((void**)&idx, g_idx);
    cudaGetSymbolAddress((void**)&p1, g_part1);
    cudaGetSymbolAddress((void**)&p2, g_part2);
    cudaGetSymbolAddress((void**)&p3, g_part3);
    cudaGetSymbolAddress((void**)&sc1, g_sc1);
    cudaGetSymbolAddress((void**)&sh1, g_sh1);
    cudaGetSymbolAddress((void**)&sc2, g_sc2);
    cudaGetSymbolAddress((void**)&sh2, g_sh2);
    cudaGetSymbolAddress((void**)&sc3, g_sc3);
    cudaGetSymbolAddress((void**)&sh3, g_sh3);
    cudaGetSymbolAddress((void**)&tick, g_tick);

    const int smem1 = (128 + 64) * 76 * 4;  // 58368
    const int smem2 = (128 + 64) * 68 * 4;  // 52224
    cudaFuncSetAttribute(mma_kernel<1>, cudaFuncAttributeMaxDynamicSharedMemorySize, smem1);
    cudaFuncSetAttribute(mma_kernel<2>, cudaFuncAttributeMaxDynamicSharedMemorySize, smem2);
    cudaFuncSetAttribute(mma_kernel<3>, cudaFuncAttributeMaxDynamicSharedMemorySize, smem2);

    // 0) reset ticket counters (required for deterministic graph replay)
    init_kernel<<<1, 32>>>();
    // 1) FPS -> new_xyz (first 49152 elems of out)
    fps_kernel<<<NB, 512>>>(xyz, out);
    // 2) ball query -> g_idx
    ball_kernel<<<(NB * NPOINT * 32) / 256, 256>>>(xyz, out, idx);
    // 3) layer1 (gather 67ch -> 64); last block emits BN1 coefs
    mma_kernel<1><<<M_TOTAL / 128, 128, smem1>>>(
        xyz, points, out, idx, nullptr, nullptr, nullptr, g1, be1,
        w1, b1, y1, p1, sc1, sh1, &tick[0]);
    // 4) layer2 (BN1+relu fused on load); last block emits BN2 coefs
    mma_kernel<2><<<M_TOTAL / 128, 128, smem2>>>(
        nullptr, nullptr, nullptr, nullptr, y1, sc1, sh1, g2, be2,
        w2, b2, y2, p2, sc2, sh2, &tick[1]);
    // 5) layer3 (BN2+relu fused on load, O=128 split over block parity)
    mma_kernel<3><<<2 * (M_TOTAL / 128), 128, smem2>>>(
        nullptr, nullptr, nullptr, nullptr, y2, sc2, sh2, g3, be3,
        w3, b3, y3, p3, sc3, sh3, &tick[2]);
    // 6) BN3 + relu + max over nsample
    final_kernel<<<NB * NPOINT, 128>>>(y3, sc3, sh3, out);
}

// round 9
// speedup vs baseline: 4.2034x; 1.6160x over previous
#include <cuda_runtime.h>
#include <cstdint>

typedef unsigned long long ull;

// Problem constants
constexpr int NB = 16, NN = 8192, NPOINT = 1024, NSAMPLE = 32;
constexpr int M_TOTAL = NB * NPOINT * NSAMPLE;       // 524288 positions
constexpr float INV_N = 1.0f / (float)M_TOTAL;       // 2^-19, exact
constexpr int NEWXYZ_ELEMS = NB * NPOINT * 3;        // 49152

// -------- scratch (device globals; no allocation allowed) --------
__device__ float g_y1[(size_t)M_TOTAL * 64];
__device__ float g_y2[(size_t)M_TOTAL * 64];
__device__ float g_y3[(size_t)M_TOTAL * 128];
__device__ int   g_idx[M_TOTAL];
__device__ float g_part1[4096 * 128];
__device__ float g_part2[4096 * 128];
__device__ float g_part3[8192 * 128];
__device__ float g_sc1[64],  g_sh1[64];
__device__ float g_sc2[64],  g_sh2[64];
__device__ float g_sc3[128], g_sh3[128];

// ---------------- helpers ----------------
__device__ __forceinline__ float to_tf32(float x) {
    unsigned u;
    asm("cvt.rna.tf32.f32 %0, %1;" : "=r"(u) : "f"(x));
    return __uint_as_float(u);
}
__device__ __forceinline__ float sqdist3(float dx, float dy, float dz) {
    return fmaf(dz, dz, fmaf(dy, dy, __fmul_rn(dx, dx)));
}
// m16n8k8 tf32 HMMA (PTX-portable on compute_103; runs on tensor pipes)
__device__ __forceinline__ void mma16n8k8(float* d, const uint32_t* a,
                                          const uint32_t* b) {
    asm volatile(
        "mma.sync.aligned.m16n8k8.row.col.f32.tf32.tf32.f32 "
        "{%0,%1,%2,%3}, {%4,%5,%6,%7}, {%8,%9}, {%0,%1,%2,%3};"
        : "+f"(d[0]), "+f"(d[1]), "+f"(d[2]), "+f"(d[3])
        : "r"(a[0]), "r"(a[1]), "r"(a[2]), "r"(a[3]), "r"(b[0]), "r"(b[1]));
}

// ---------------- 1) farthest point sampling ----------------
// One block per batch; 512 threads x 16 points in registers.
// xyz mirrored in smem so all threads fetch the new centroid directly.
// One __syncthreads per iteration (double-buffered warp results).
__global__ void __launch_bounds__(512) fps_kernel(const float* __restrict__ xyz,
                                                  float* __restrict__ newxyz) {
    extern __shared__ float sx[];   // [NN*3]
    const int b = blockIdx.x, tid = threadIdx.x;
    const float* X = xyz + (size_t)b * NN * 3;
    float px[16], py[16], pz[16], dd[16];
#pragma unroll
    for (int j = 0; j < 16; j++) {
        int p = tid * 16 + j;
        px[j] = X[p * 3 + 0]; py[j] = X[p * 3 + 1]; pz[j] = X[p * 3 + 2];
        dd[j] = 1e10f;
    }
    for (int e = tid; e < NN * 3; e += 512) sx[e] = X[e];

    __shared__ int swv[2][16];
    __shared__ int swi[2][16];
    __syncthreads();

    float cx = sx[0], cy = sx[1], cz = sx[2];
    float* outb = newxyz + (size_t)b * NPOINT * 3;
    const int lane = tid & 31, wid = tid >> 5;
    int buf = 0;

    for (int it = 0; it < NPOINT; ++it) {
        if (tid == 0) {
            outb[it * 3 + 0] = cx;
            outb[it * 3 + 1] = cy;
            outb[it * 3 + 2] = cz;
        }
        float best = -1.0f; int bi = 0;
#pragma unroll
        for (int j = 0; j < 16; j++) {
            float dx = __fsub_rn(px[j], cx);
            float dy = __fsub_rn(py[j], cy);
            float dz = __fsub_rn(pz[j], cz);
            float d = sqdist3(dx, dy, dz);
            float nd = fminf(dd[j], d);
            dd[j] = nd;
            if (nd > best) { best = nd; bi = tid * 16 + j; }
        }
        // warp argmax: nonneg float bits compare as ints; ballot -> min-index tie
        int vb = __float_as_int(best);
        int wmax = __reduce_max_sync(0xffffffffu, vb);
        unsigned msk = __ballot_sync(0xffffffffu, vb == wmax);
        int ldr = __ffs(msk) - 1;
        int widx = __shfl_sync(0xffffffffu, bi, ldr);
        if (lane == 0) { swv[buf][wid] = wmax; swi[buf][wid] = widx; }
        __syncthreads();
        // all warps redundantly reduce the 16 warp results
        int l = lane & 15;
        int v2 = swv[buf][l], i2 = swi[buf][l];
        int m2 = __reduce_max_sync(0xffffffffu, v2);
        unsigned mk2 = __ballot_sync(0xffffffffu, v2 == m2);
        int l2 = __ffs(mk2) - 1;                 // lands in 0..15 (mirrored halves)
        int f = __shfl_sync(0xffffffffu, i2, l2);
        cx = sx[f * 3 + 0]; cy = sx[f * 3 + 1]; cz = sx[f * 3 + 2];
        buf ^= 1;
    }
}

// ---------------- 2) ball query ----------------
__global__ void __launch_bounds__(256) ball_kernel(const float* __restrict__ xyz,
                                                   const float* __restrict__ newxyz,
                                                   int* __restrict__ gidx) {
    const int gwarp = (blockIdx.x * blockDim.x + threadIdx.x) >> 5;
    const int lane = threadIdx.x & 31;
    if (gwarp >= NB * NPOINT) return;
    const int b = gwarp >> 10;
    const float R2 = (float)(0.2 * 0.2);

    const float cx = newxyz[gwarp * 3 + 0];
    const float cy = newxyz[gwarp * 3 + 1];
    const float cz = newxyz[gwarp * 3 + 2];
    const float* X = xyz + (size_t)b * NN * 3;
    int* out = gidx + (size_t)gwarp * NSAMPLE;

    int cnt = 0;
    int first = NN - 1;
    for (int base = 0; base < NN; base += 32) {
        int j = base + lane;
        float dx = __fsub_rn(cx, X[j * 3 + 0]);
        float dy = __fsub_rn(cy, X[j * 3 + 1]);
        float dz = __fsub_rn(cz, X[j * 3 + 2]);
        float sq = sqdist3(dx, dy, dz);
        bool in = !(sq > R2);
        unsigned mask = __ballot_sync(0xffffffffu, in);
        if (mask) {
            if (cnt == 0) first = base + __ffs(mask) - 1;
            if (in) {
                int slot = cnt + __popc(mask & ((1u << lane) - 1u));
                if (slot < NSAMPLE) out[slot] = j;
            }
            cnt += __popc(mask);
            if (cnt >= NSAMPLE) break;
        }
    }
    if (cnt < NSAMPLE && lane >= cnt) out[lane] = first;
}

// ---------------- 3) HMMA tf32 GEMM per layer (K-split, 2 stages) ----------------
// Block = 128 threads (4 warps), tile = 128 positions x 64 outputs.
// A tile staged in two K-chunks (smem -> 5 blocks/SM).
// MODE 1: gather grouped features (67 ch).  MODE 2: y1->y2.  MODE 3: y2->y3.
template <int MODE>
__global__ void __launch_bounds__(128) mma_kernel(
    const float* __restrict__ xyz, const float* __restrict__ points,
    const float* __restrict__ newxyz, const int* __restrict__ gidx,
    const float* __restrict__ yin,
    const float* __restrict__ scin, const float* __restrict__ shin,
    const float* __restrict__ W, const float* __restrict__ bias,
    float* __restrict__ yout, float* __restrict__ part) {
    constexpr int CIN = (MODE == 1) ? 67 : 64;
    constexpr int KP  = (MODE == 1) ? 72 : 64;
    constexpr int S0  = (MODE == 1) ? 40 : 32;   // stage-0 cols
    constexpr int S1  = KP - S0;                 // 32
    constexpr int STR_A = S0 + 4;                // 44 / 36
    constexpr int STR_B = KP + 4;                // 76 / 68
    constexpr int NK0 = S0 / 8, NK1 = S1 / 8;
    constexpr int OSTRIDE = (MODE == 3) ? 128 : 64;

    extern __shared__ float sm[];
    float* As = sm;                    // [128][STR_A]
    float* Bs = sm + 128 * STR_A;      // [64][STR_B]
    __shared__ float sSc[64], sSh[64], sBias[64];
    __shared__ float sNew[4][3];
    __shared__ float redS[2][64], redQ[2][64];

    const int tid = threadIdx.x;
    const int lane = tid & 31, w = tid >> 5;
    int m_tile, obase;
    if (MODE == 3) { m_tile = blockIdx.x >> 1; obase = (blockIdx.x & 1) << 6; }
    else           { m_tile = blockIdx.x;      obase = 0; }
    const int m0 = m_tile * 128;

    if (tid < 64) sBias[tid] = bias[obase + tid];
    if (MODE == 1) {
        if (tid < 12) ((float*)sNew)[tid] = newxyz[(m0 >> 5) * 3 + tid];
    } else {
        if (tid >= 64) { sSc[tid - 64] = scin[tid - 64]; sSh[tid - 64] = shin[tid - 64]; }
    }
    __syncthreads();

    // ---- B (weights, full K) ----
    for (int e = tid; e < 64 * KP; e += 128) {
        int o = e / KP, c = e - o * KP;
        Bs[o * STR_B + c] = (c < CIN) ? to_tf32(W[(obase + o) * CIN + c]) : 0.0f;
    }

    // ---- A pointers ----
    const int m = tid;
    float* Arow = As + m * STR_A;
    const float* Pb = nullptr;
    const float4* yrow = nullptr;
    if (MODE == 1) {
        const int bb = m0 >> 15;
        const int gi = gidx[m0 + m];
        Pb = points + ((size_t)bb * NN + gi) * 64;
        const float* Xb = xyz + ((size_t)bb * NN + gi) * 3;
        // stage 0: cols 0..39 = [xyz-norm(3), points 0..36]
        float4 t[10];
#pragma unroll
        for (int j = 0; j < 10; j++) t[j] = reinterpret_cast<const float4*>(Pb)[j];
        Arow[0] = to_tf32(__fsub_rn(Xb[0], sNew[m >> 5][0]));
        Arow[1] = to_tf32(__fsub_rn(Xb[1], sNew[m >> 5][1]));
        Arow[2] = to_tf32(__fsub_rn(Xb[2], sNew[m >> 5][2]));
#pragma unroll
        for (int c = 3; c < 40; c++) Arow[c] = to_tf32(((float*)t)[c - 3]);
    } else {
        yrow = reinterpret_cast<const float4*>(&yin[(size_t)(m0 + m) * 64]);
#pragma unroll
        for (int q = 0; q < 8; q++) {
            float4 v = yrow[q];
            int c = q * 4;
            v.x = to_tf32(fmaxf(fmaf(v.x, sSc[c + 0], sSh[c + 0]), 0.0f));
            v.y = to_tf32(fmaxf(fmaf(v.y, sSc[c + 1], sSh[c + 1]), 0.0f));
            v.z = to_tf32(fmaxf(fmaf(v.z, sSc[c + 2], sSh[c + 2]), 0.0f));
            v.w = to_tf32(fmaxf(fmaf(v.w, sSc[c + 3], sSh[c + 3]), 0.0f));
            *reinterpret_cast<float4*>(Arow + c) = v;
        }
    }
    __syncthreads();

    const int r = lane >> 2, cq = lane & 3;
    float acc[16][4];
#pragma unroll
    for (int i = 0; i < 16; i++) {
        acc[i][0] = 0.0f; acc[i][1] = 0.0f; acc[i][2] = 0.0f; acc[i][3] = 0.0f;
    }

    // ---- stage 0 MMA ----
#pragma unroll
    for (int ks = 0; ks < NK0; ks++) {
        const int kl = ks * 8;
        uint32_t a[2][4];
#pragma unroll
        for (int mt = 0; mt < 2; mt++) {
            const float* p = As + (w * 32 + mt * 16 + r) * STR_A + kl + cq;
            a[mt][0] = __float_as_uint(p[0]);
            a[mt][1] = __float_as_uint(p[8 * STR_A]);
            a[mt][2] = __float_as_uint(p[4]);
            a[mt][3] = __float_as_uint(p[8 * STR_A + 4]);
        }
#pragma unroll
        for (int nt = 0; nt < 8; nt++) {
            const float* q = Bs + (nt * 8 + r) * STR_B + kl + cq;
            uint32_t bfr[2];
            bfr[0] = __float_as_uint(q[0]);
            bfr[1] = __float_as_uint(q[4]);
            mma16n8k8(acc[nt], a[0], bfr);
            mma16n8k8(acc[8 + nt], a[1], bfr);
        }
    }
    __syncthreads();

    // ---- A stage 1 ----
    if (MODE == 1) {
        // cols 40..71 -> points 37..63, zero pad 67..71
        float4 t2[7];
#pragma unroll
        for (int j = 0; j < 7; j++) t2[j] = reinterpret_cast<const float4*>(Pb)[9 + j];
#pragma unroll
        for (int cc = 0; cc < 32; cc++)
            Arow[cc] = (cc < 27) ? to_tf32(((float*)t2)[cc + 1]) : 0.0f;
    } else {
#pragma unroll
        for (int q = 8; q < 16; q++) {
            float4 v = yrow[q];
            int c = q * 4;
            v.x = to_tf32(fmaxf(fmaf(v.x, sSc[c + 0], sSh[c + 0]), 0.0f));
            v.y = to_tf32(fmaxf(fmaf(v.y, sSc[c + 1], sSh[c + 1]), 0.0f));
            v.z = to_tf32(fmaxf(fmaf(v.z, sSc[c + 2], sSh[c + 2]), 0.0f));
            v.w = to_tf32(fmaxf(fmaf(v.w, sSc[c + 3], sSh[c + 3]), 0.0f));
            *reinterpret_cast<float4*>(Arow + (q - 8) * 4) = v;
        }
    }
    __syncthreads();

    // ---- stage 1 MMA ----
#pragma unroll
    for (int ks = 0; ks < NK1; ks++) {
        const int kl = ks * 8, kg = S0 + ks * 8;
        uint32_t a[2][4];
#pragma unroll
        for (int mt = 0; mt < 2; mt++) {
            const float* p = As + (w * 32 + mt * 16 + r) * STR_A + kl + cq;
            a[mt][0] = __float_as_uint(p[0]);
            a[mt][1] = __float_as_uint(p[8 * STR_A]);
            a[mt][2] = __float_as_uint(p[4]);
            a[mt][3] = __float_as_uint(p[8 * STR_A + 4]);
        }
#pragma unroll
        for (int nt = 0; nt < 8; nt++) {
            const float* q = Bs + (nt * 8 + r) * STR_B + kg + cq;
            uint32_t bfr[2];
            bfr[0] = __float_as_uint(q[0]);
            bfr[1] = __float_as_uint(q[4]);
            mma16n8k8(acc[nt], a[0], bfr);
            mma16n8k8(acc[8 + nt], a[1], bfr);
        }
    }
    __syncthreads();   // A/B smem dead; reuse as ys[128][65]

    // ---- epilogue: bias add, scatter to ys[m][o] ----
    float* ys = sm;
#pragma unroll
    for (int mt = 0; mt < 2; mt++) {
#pragma unroll
        for (int nt = 0; nt < 8; nt++) {
            const int row = w * 32 + mt * 16 + r;
            const int col = nt * 8 + 2 * cq;
            const float* c = acc[mt * 8 + nt];
            ys[row * 65 + col]           = c[0] + sBias[col];
            ys[row * 65 + col + 1]       = c[1] + sBias[col + 1];
            ys[(row + 8) * 65 + col]     = c[2] + sBias[col];
            ys[(row + 8) * 65 + col + 1] = c[3] + sBias[col + 1];
        }
    }
    __syncthreads();

    // block stats (deterministic order)
    {
        const int o = tid & 63, h = tid >> 6;
        float s = 0.0f, ss = 0.0f;
#pragma unroll 8
        for (int i = 0; i < 64; i++) {
            float v = ys[(h * 64 + i) * 65 + o];
            s += v; ss += v * v;
        }
        redS[h][o] = s; redQ[h][o] = ss;
    }
    __syncthreads();
    if (tid < 64) {
        part[blockIdx.x * 128 + tid] = redS[0][tid] + redS[1][tid];
        part[blockIdx.x * 128 + 64 + tid] = redQ[0][tid] + redQ[1][tid];
    }
    // coalesced y write
    for (int e = tid; e < 8192; e += 128) {
        int mm = e >> 6, o = e & 63;
        yout[(size_t)(m0 + mm) * OSTRIDE + obase + o] = ys[mm * 65 + o];
    }
}

// ---------------- 4) BN stats reduction -> scale/shift (deterministic) ----------------
template <int NCH>
__global__ void __launch_bounds__(256) reduce_kernel(const float* __restrict__ part,
                                                     const float* __restrict__ pg,
                                                     const float* __restrict__ pbe,
                                                     float* __restrict__ scout,
                                                     float* __restrict__ shout,
                                                     int nrows) {
    const int ch = blockIdx.x;
    float s = 0.0f, ss = 0.0f;
    if (NCH == 64) {
        for (int rr = threadIdx.x; rr < nrows; rr += 256) {
            s += part[rr * 128 + ch];
            ss += part[rr * 128 + 64 + ch];
        }
    } else {
        const int p = ch >> 6, lc = ch & 63;
        const int half = nrows >> 1;
        for (int i = threadIdx.x; i < half; i += 256) {
            int rr = 2 * i + p;
            s += part[rr * 128 + lc];
            ss += part[rr * 128 + 64 + lc];
        }
    }
    __shared__ float as_[8], bs_[8];
#pragma unroll
    for (int off = 16; off; off >>= 1) {
        s += __shfl_down_sync(0xffffffffu, s, off);
        ss += __shfl_down_sync(0xffffffffu, ss, off);
    }
    const int lane = threadIdx.x & 31, wid = threadIdx.x >> 5;
    if (lane == 0) { as_[wid] = s; bs_[wid] = ss; }
    __syncthreads();
    if (threadIdx.x == 0) {
        float S = 0.0f, Q = 0.0f;
        for (int i = 0; i < 8; i++) { S += as_[i]; Q += bs_[i]; }
        float mean = S * INV_N;
        float var = Q * INV_N - mean * mean;
        float inv = rsqrtf(var + 1e-5f);
        float scv = pg[ch] * inv;
        scout[ch] = scv;
        shout[ch] = pbe[ch] - mean * scv;
    }
}

// ---------------- 5) BN3 + ReLU + max over k ----------------
__global__ void __launch_bounds__(128) final_kernel(const float* __restrict__ y3,
                                                    const float* __restrict__ sc3,
                                                    const float* __restrict__ sh3,
                                                    float* __restrict__ out) {
    const int q = blockIdx.x;      // b*1024 + s
    const int o = threadIdx.x;     // channel 0..127
    float scv = sc3[o], sh = sh3[o];
    const float* base = y3 + (size_t)q * NSAMPLE * 128;
    float mx = -1e30f;
#pragma unroll 8
    for (int k = 0; k < NSAMPLE; k++) {
        float v = base[k * 128 + o];
        v = fmaxf(fmaf(v, scv, sh), 0.0f);
        mx = fmaxf(mx, v);
    }
    const int b = q >> 10, si = q & 1023;
    out[NEWXYZ_ELEMS + ((size_t)(b * 128 + o)) * 1024 + si] = mx;
}

// ---------------- launch ----------------
extern "C" void kernel_launch(void* const* d_in, const int* in_sizes, int n_in,
                              void* d_out, int out_size) {
    const float* xyz    = (const float*)d_in[0];
    const float* points = (const float*)d_in[1];
    const float* w1 = (const float*)d_in[2];
    const float* b1 = (const float*)d_in[3];
    const float* g1 = (const float*)d_in[4];
    const float* be1 = (const float*)d_in[5];
    const float* w2 = (const float*)d_in[6];
    const float* b2 = (const float*)d_in[7];
    const float* g2 = (const float*)d_in[8];
    const float* be2 = (const float*)d_in[9];
    const float* w3 = (const float*)d_in[10];
    const float* b3 = (const float*)d_in[11];
    const float* g3 = (const float*)d_in[12];
    const float* be3 = (const float*)d_in[13];
    float* out = (float*)d_out;

    float *y1, *y2, *y3, *p1, *p2, *p3;
    float *sc1, *sh1, *sc2, *sh2, *sc3, *sh3;
    int* idx;
    cudaGetSymbolAddress((void**)&y1, g_y1);
    cudaGetSymbolAddress((void**)&y2, g_y2);
    cudaGetSymbolAddress((void**)&y3, g_y3);
    cudaGetSymbolAddress((void**)&idx, g_idx);
    cudaGetSymbolAddress((void**)&p1, g_part1);
    cudaGetSymbolAddress((void**)&p2, g_part2);
    cudaGetSymbolAddress((void**)&p3, g_part3);
    cudaGetSymbolAddress((void**)&sc1, g_sc1);
    cudaGetSymbolAddress((void**)&sh1, g_sh1);
    cudaGetSymbolAddress((void**)&sc2, g_sc2);
    cudaGetSymbolAddress((void**)&sh2, g_sh2);
    cudaGetSymbolAddress((void**)&sc3, g_sc3);
    cudaGetSymbolAddress((void**)&sh3, g_sh3);

    const int smemF = NN * 3 * 4;                      // 98304 (fps)
    const int smem1 = (128 * 44 + 64 * 76) * 4;        // 41984
    const int smem2 = (128 * 36 + 64 * 68) * 4;        // 35840
    cudaFuncSetAttribute(fps_kernel, cudaFuncAttributeMaxDynamicSharedMemorySize, smemF);
    cudaFuncSetAttribute(mma_kernel<1>, cudaFuncAttributeMaxDynamicSharedMemorySize, smem1);
    cudaFuncSetAttribute(mma_kernel<2>, cudaFuncAttributeMaxDynamicSharedMemorySize, smem2);
    cudaFuncSetAttribute(mma_kernel<3>, cudaFuncAttributeMaxDynamicSharedMemorySize, smem2);

    // 1) FPS -> new_xyz (first 49152 elems of out)
    fps_kernel<<<NB, 512, smemF>>>(xyz, out);
    // 2) ball query -> g_idx
    ball_kernel<<<(NB * NPOINT * 32) / 256, 256>>>(xyz, out, idx);
    // 3) layer1 (gather 67ch -> 64)
    mma_kernel<1><<<M_TOTAL / 128, 128, smem1>>>(
        xyz, points, out, idx, nullptr, nullptr, nullptr, w1, b1, y1, p1);
    reduce_kernel<64><<<64, 256>>>(p1, g1, be1, sc1, sh1, 4096);
    // 4) layer2 (BN1+relu fused on load)
    mma_kernel<2><<<M_TOTAL / 128, 128, smem2>>>(
        nullptr, nullptr, nullptr, nullptr, y1, sc1, sh1, w2, b2, y2, p2);
    reduce_kernel<64><<<64, 256>>>(p2, g2, be2, sc2, sh2, 4096);
    // 5) layer3 (BN2+relu fused on load, O=128 split over block parity)
    mma_kernel<3><<<2 * (M_TOTAL / 128), 128, smem2>>>(
        nullptr, nullptr, nullptr, nullptr, y2, sc2, sh2, w3, b3, y3, p3);
    reduce_kernel<128><<<128, 256>>>(p3, g3, be3, sc3, sh3, 8192);
    // 6) BN3 + relu + max over nsample
    final_kernel<<<NB * NPOINT, 128>>>(y3, sc3, sh3, out);
}